// round 8
// baseline (speedup 1.0000x reference)
#include <cuda_runtime.h>

#define B  16
#define TE 128
#define TD 128
#define H  256

typedef unsigned long long ull;

// Scratch (no allocation allowed -> __device__ globals)
__device__ float g_ortho[B*TE*H];
__device__ float g_was[B*TE*H];
__device__ float g_uah[B*TD*H];

__device__ __forceinline__ float tanh_fast(float x) {
    float y;
    asm("tanh.approx.f32 %0, %1;" : "=f"(y) : "f"(x));
    return y;
}
__device__ __forceinline__ ull pack2(float lo, float hi) {
    ull r; asm("mov.b64 %0, {%1, %2};" : "=l"(r) : "f"(lo), "f"(hi)); return r;
}
__device__ __forceinline__ void unpack2(ull v, float& lo, float& hi) {
    asm("mov.b64 {%0, %1}, %2;" : "=f"(lo), "=f"(hi) : "l"(v));
}
// packed fp32x2 FMA (Blackwell FFMA2): d = a*b + d
__device__ __forceinline__ void fma2(ull& d, ull a, ull b) {
    asm("fma.rn.f32x2 %0, %1, %2, %0;" : "+l"(d) : "l"(a), "l"(b));
}

// ---------------------------------------------------------------------------
// Ortho part (device fn): segmented prefix scan.
// 128 threads = 32 h x 4 t-segments of 32. bx in [0,128): b = bx>>3, hc = bx&7.
// ---------------------------------------------------------------------------
__device__ __forceinline__ void ortho_part(const float* __restrict__ enc, int bx) {
    __shared__ float segsum[4][32];
    int tid = threadIdx.x;
    int hl  = tid & 31;
    int seg = tid >> 5;                 // 0..3
    int b   = bx >> 3;
    int h   = (bx & 7) * 32 + hl;

    const float* p = enc     + (size_t)(b*TE + seg*32)*H + h;
    float*       q = g_ortho + (size_t)(b*TE + seg*32)*H + h;

    float x[32];
    #pragma unroll
    for (int u = 0; u < 32; u++) x[u] = p[u*H];

    float loc = 0.f;
    #pragma unroll
    for (int u = 0; u < 32; u++) loc += x[u];
    segsum[seg][hl] = loc;
    __syncthreads();
    float s = 0.f;
    #pragma unroll
    for (int ss = 0; ss < 3; ss++)
        if (ss < seg) s += segsum[ss][hl];

    #pragma unroll
    for (int u = 0; u < 32; u++) {
        float xv = x[u];
        float r = __fdividef(xv*s, xv*xv);
        q[u*H] = xv - r*xv;
        s += xv;
    }
}

// ---------------------------------------------------------------------------
// GEMM tile (device fn): C[2048,256] = A[2048,256] @ W[256,256]
// 64x64 tile, 128 threads, 8m x 4n micro-tile via diagonal-pair FFMA2.
// tileIdx in [0,128): m0 = (tileIdx>>2)*64, n0 = (tileIdx&3)*64.
// Register-prefetch pipeline over 16 k-chunks of depth 16.
// ---------------------------------------------------------------------------
__device__ __forceinline__ void gemm_tile(const float* __restrict__ A,
                                          const float* __restrict__ W,
                                          float* __restrict__ C, int tileIdx) {
    __shared__ float As[16][64];   // [k][m] (m contiguous -> natural m-pairs)
    __shared__ float Ws[16][64];   // [k][n]

    int tid = threadIdx.x;
    int m0 = (tileIdx >> 2) * 64;
    int n0 = (tileIdx & 3) * 64;
    int tx = tid & 15;             // n-group (4 cols)
    int ty = tid >> 4;             // m-group (8 rows)

    int lm = tid >> 1;             // A load row 0..63
    int lq = (tid & 1) * 2;        // which float4 pair of the 4 in a 16k row
    int wk = tid >> 3;             // W load k 0..15
    int wq = tid & 7;              // 8-col group

    const float* Arow = A + (size_t)(m0 + lm)*256 + lq*4;
    const float* Wrow = W + (size_t)wk*256 + n0 + wq*8;

    float4 Ar0, Ar1, Wr0, Wr1;
    Ar0 = *reinterpret_cast<const float4*>(Arow);
    Ar1 = *reinterpret_cast<const float4*>(Arow + 4);
    Wr0 = *reinterpret_cast<const float4*>(Wrow);
    Wr1 = *reinterpret_cast<const float4*>(Wrow + 4);

    ull aD[4][2], aA[4][2];
    #pragma unroll
    for (int i = 0; i < 4; i++) { aD[i][0]=0; aD[i][1]=0; aA[i][0]=0; aA[i][1]=0; }

    #pragma unroll 1
    for (int c = 0; c < 16; c++) {
        __syncthreads();
        As[lq*4+0][lm] = Ar0.x; As[lq*4+1][lm] = Ar0.y;
        As[lq*4+2][lm] = Ar0.z; As[lq*4+3][lm] = Ar0.w;
        As[lq*4+4][lm] = Ar1.x; As[lq*4+5][lm] = Ar1.y;
        As[lq*4+6][lm] = Ar1.z; As[lq*4+7][lm] = Ar1.w;
        *reinterpret_cast<float4*>(&Ws[wk][wq*8])     = Wr0;
        *reinterpret_cast<float4*>(&Ws[wk][wq*8 + 4]) = Wr1;
        __syncthreads();
        if (c < 15) {
            Ar0 = *reinterpret_cast<const float4*>(Arow + (c+1)*16);
            Ar1 = *reinterpret_cast<const float4*>(Arow + (c+1)*16 + 4);
            Wr0 = *reinterpret_cast<const float4*>(Wrow + (size_t)(c+1)*16*256);
            Wr1 = *reinterpret_cast<const float4*>(Wrow + (size_t)(c+1)*16*256 + 4);
        }
        #pragma unroll
        for (int k = 0; k < 16; k++) {
            const ull* ap = reinterpret_cast<const ull*>(&As[k][ty*8]);  // 4 m-pairs
            float4 wv = *reinterpret_cast<const float4*>(&Ws[k][tx*4]);
            ull w01 = pack2(wv.x, wv.y), w23 = pack2(wv.z, wv.w);
            ull s01 = pack2(wv.y, wv.x), s23 = pack2(wv.w, wv.z);
            #pragma unroll
            for (int i = 0; i < 4; i++) {
                ull a = ap[i];
                fma2(aD[i][0], a, w01);
                fma2(aD[i][1], a, w23);
                fma2(aA[i][0], a, s01);
                fma2(aA[i][1], a, s23);
            }
        }
    }

    // Epilogue: diag/anti-diag -> rows
    #pragma unroll
    for (int i = 0; i < 4; i++) {
        float d0l,d0h,d1l,d1h,a0l,a0h,a1l,a1h;
        unpack2(aD[i][0], d0l, d0h); unpack2(aD[i][1], d1l, d1h);
        unpack2(aA[i][0], a0l, a0h); unpack2(aA[i][1], a1l, a1h);
        float4 r0; r0.x = d0l; r0.y = a0l; r0.z = d1l; r0.w = a1l;
        float4 r1; r1.x = a0h; r1.y = d0h; r1.z = a1h; r1.w = d1h;
        float* cp = C + (size_t)(m0 + ty*8 + 2*i)*256 + n0 + tx*4;
        *reinterpret_cast<float4*>(cp)       = r0;
        *reinterpret_cast<float4*>(cp + 256) = r1;
    }
}

// ---------------------------------------------------------------------------
// K1: ortho (128 CTAs) + uah GEMM (128 CTAs) fused in one launch.
// ---------------------------------------------------------------------------
__global__ void prep_kernel(const float* __restrict__ enc,
                            const float* __restrict__ dec,
                            const float* __restrict__ Ua) {
    if (blockIdx.x < 128) ortho_part(enc, blockIdx.x);
    else                  gemm_tile(dec, Ua, g_uah, blockIdx.x - 128);
}

// K2: was = ortho @ W_a (depends on ortho)
__global__ void was_kernel(const float* __restrict__ Wa) {
    gemm_tile(g_ortho, Wa, g_was, blockIdx.x);
}

// ---------------------------------------------------------------------------
// K3: energy + softmax + context, per (b, 16-d tile). 128 CTAs x 256 threads.
// ---------------------------------------------------------------------------
__global__ void attn_kernel(const float* __restrict__ Va,
                            float* __restrict__ c_out,
                            float* __restrict__ e_out) {
    __shared__ float  u_sm[16][H];        // 16 KB
    __shared__ float  V_sm[H];            // 1 KB
    __shared__ float  en_sm[16][TE];      // 8 KB
    __shared__ float2 en2_sm[8][TE];      // 8 KB packed prob pairs

    int b   = blockIdx.x >> 3;
    int d0  = (blockIdx.x & 7) * 16;
    int tid = threadIdx.x;
    int warp = tid >> 5, lane = tid & 31;

    {   // u_sm: 16 rows x 256 = 1024 float4
        const float4* usrc = reinterpret_cast<const float4*>(g_uah + (size_t)(b*TD + d0)*H);
        float4* udst = reinterpret_cast<float4*>(&u_sm[0][0]);
        #pragma unroll
        for (int r = 0; r < 4; r++) udst[tid + 256*r] = usrc[tid + 256*r];
        V_sm[tid] = Va[tid];
    }
    __syncthreads();

    const float* wbase = g_was + (size_t)(b*TE)*H;

    // ---- energies: warp handles e = pass*8 + warp, 16 passes, 16 d accs ----
    float w[8];
    {
        const float* wr = wbase + warp*H;
        #pragma unroll
        for (int j = 0; j < 8; j++) w[j] = wr[lane + 32*j];
    }
    #pragma unroll 1
    for (int pass = 0; pass < 16; pass++) {
        int e = pass*8 + warp;
        float wn[8];
        if (pass < 15) {
            const float* wr = wbase + (e + 8)*H;
            #pragma unroll
            for (int j = 0; j < 8; j++) wn[j] = wr[lane + 32*j];
        }
        float a[16];
        #pragma unroll
        for (int d = 0; d < 16; d++) a[d] = 0.f;
        #pragma unroll
        for (int j = 0; j < 8; j++) {
            int hh = lane + 32*j;
            float wv = w[j];
            float v  = V_sm[hh];
            #pragma unroll
            for (int d = 0; d < 16; d++)
                a[d] += tanh_fast(wv + u_sm[d][hh]) * v;
        }
        #pragma unroll
        for (int off = 16; off; off >>= 1)
            #pragma unroll
            for (int d = 0; d < 16; d++)
                a[d] += __shfl_xor_sync(0xffffffffu, a[d], off);
        if (lane == 0) {
            #pragma unroll
            for (int d = 0; d < 16; d++) en_sm[d][e] = a[d];
        }
        #pragma unroll
        for (int j = 0; j < 8; j++) w[j] = wn[j];
    }
    __syncthreads();

    // ---- softmax over e: each warp handles rows d = warp and warp+8 ----
    #pragma unroll
    for (int dd = 0; dd < 2; dd++) {
        int d = warp + dd*8;
        float v0 = en_sm[d][lane],     v1 = en_sm[d][lane+32];
        float v2 = en_sm[d][lane+64],  v3 = en_sm[d][lane+96];
        float m = fmaxf(fmaxf(v0, v1), fmaxf(v2, v3));
        #pragma unroll
        for (int off = 16; off; off >>= 1)
            m = fmaxf(m, __shfl_xor_sync(0xffffffffu, m, off));
        v0 = __expf(v0 - m); v1 = __expf(v1 - m);
        v2 = __expf(v2 - m); v3 = __expf(v3 - m);
        float s = v0 + v1 + v2 + v3;
        #pragma unroll
        for (int off = 16; off; off >>= 1)
            s += __shfl_xor_sync(0xffffffffu, s, off);
        float inv = 1.0f / s;
        v0 *= inv; v1 *= inv; v2 *= inv; v3 *= inv;
        float* er = e_out + (size_t)(b*TD + d0 + d)*TE;
        er[lane]    = v0; er[lane+32] = v1;
        er[lane+64] = v2; er[lane+96] = v3;
        float* dst = reinterpret_cast<float*>(&en2_sm[d>>1][0]) + (d & 1);
        dst[2*lane]      = v0; dst[2*(lane+32)] = v1;
        dst[2*(lane+64)] = v2; dst[2*(lane+96)] = v3;
    }
    __syncthreads();

    // ---- context: c[d][h] = sum_e p[d][e] * ortho[b,e,h], f32x2 packed ----
    {
        int hh = tid;
        const float* orow = g_ortho + (size_t)(b*TE)*H + hh;
        ull acc[8];
        #pragma unroll
        for (int p = 0; p < 8; p++) acc[p] = 0ull;
        #pragma unroll 4
        for (int e = 0; e < TE; e++) {
            float x = orow[e*H];
            ull xx = pack2(x, x);
            #pragma unroll
            for (int p = 0; p < 8; p++)
                fma2(acc[p], xx, *reinterpret_cast<const ull*>(&en2_sm[p][e]));
        }
        float c[16];
        #pragma unroll
        for (int p = 0; p < 8; p++) unpack2(acc[p], c[2*p], c[2*p+1]);
        #pragma unroll
        for (int d = 0; d < 16; d++)
            c_out[(size_t)(b*TD + d0 + d)*H + hh] = c[d];
    }
}

// ---------------------------------------------------------------------------
extern "C" void kernel_launch(void* const* d_in, const int* in_sizes, int n_in,
                              void* d_out, int out_size) {
    const float* enc = (const float*)d_in[0];
    const float* dec = (const float*)d_in[1];
    const float* Wa  = (const float*)d_in[2];
    const float* Ua  = (const float*)d_in[3];
    const float* Va  = (const float*)d_in[4];

    float* out   = (float*)d_out;
    float* c_out = out;                    // [B, TD, H]
    float* e_out = out + (size_t)B*TD*H;   // [B, TD, TE]

    prep_kernel<<<256, 128>>>(enc, dec, Ua);   // ortho + uah gemm, overlapped
    was_kernel<<<128, 128>>>(Wa);              // was = ortho @ W_a
    attn_kernel<<<128, 256>>>(Va, c_out, e_out);
}

// round 12
// speedup vs baseline: 1.1214x; 1.1214x over previous
#include <cuda_runtime.h>

#define B  16
#define TE 128
#define TD 128
#define H  256

typedef unsigned long long ull;

// Scratch (no allocation allowed -> __device__ globals)
__device__ float g_ortho[B*TE*H];
__device__ float g_was[B*TE*H];
__device__ float g_uah[B*TD*H];

__device__ __forceinline__ float tanh_fast(float x) {
    float y;
    asm("tanh.approx.f32 %0, %1;" : "=f"(y) : "f"(x));
    return y;
}
__device__ __forceinline__ ull pack2(float lo, float hi) {
    ull r; asm("mov.b64 %0, {%1, %2};" : "=l"(r) : "f"(lo), "f"(hi)); return r;
}
__device__ __forceinline__ void unpack2(ull v, float& lo, float& hi) {
    asm("mov.b64 {%0, %1}, %2;" : "=f"(lo), "=f"(hi) : "l"(v));
}
// packed fp32x2 FMA (Blackwell FFMA2): d = a*b + d
__device__ __forceinline__ void fma2(ull& d, ull a, ull b) {
    asm("fma.rn.f32x2 %0, %1, %2, %0;" : "+l"(d) : "l"(a), "l"(b));
}

// ---------------------------------------------------------------------------
// Ortho (device fn): segmented prefix scan, 256 threads.
// bx in [0,64): b = bx>>2, h-block = (bx&3)*64. tid -> (seg = tid>>6, hl = tid&63).
// Each thread owns a 32-long t-segment of chain (b,h); 32 LDG in flight.
// ---------------------------------------------------------------------------
__device__ __forceinline__ void ortho_part(const float* __restrict__ enc, int bx) {
    __shared__ float segsum[4][64];
    int tid = threadIdx.x;
    int hl  = tid & 63;
    int seg = tid >> 6;                 // 0..3
    int b   = bx >> 2;
    int h   = (bx & 3) * 64 + hl;

    const float* p = enc     + (size_t)(b*TE + seg*32)*H + h;
    float*       q = g_ortho + (size_t)(b*TE + seg*32)*H + h;

    float x[32];
    #pragma unroll
    for (int u = 0; u < 32; u++) x[u] = p[u*H];

    float loc = 0.f;
    #pragma unroll
    for (int u = 0; u < 32; u++) loc += x[u];
    segsum[seg][hl] = loc;
    __syncthreads();
    float s = 0.f;
    #pragma unroll
    for (int ss = 0; ss < 3; ss++)
        if (ss < seg) s += segsum[ss][hl];

    #pragma unroll
    for (int u = 0; u < 32; u++) {
        float xv = x[u];
        float r = __fdividef(xv*s, xv*xv);
        q[u*H] = xv - r*xv;
        s += xv;
    }
}

// ---------------------------------------------------------------------------
// GEMM tile (device fn): C[2048,256] = A[2048,256] @ W[256,256]
// 64x64 tile, 256 threads, 4m x 4n micro-tile via diagonal-pair FFMA2.
// tileIdx in [0,128): m0 = (tileIdx>>2)*64, n0 = (tileIdx&3)*64.
// Register-prefetch pipeline over 16 k-chunks of depth 16.
// ---------------------------------------------------------------------------
__device__ __forceinline__ void gemm_tile(const float* __restrict__ A,
                                          const float* __restrict__ W,
                                          float* __restrict__ C, int tileIdx) {
    __shared__ float As[16][64];   // [k][m] (m contiguous -> natural m-pairs)
    __shared__ float Ws[16][64];   // [k][n]

    int tid = threadIdx.x;
    int m0 = (tileIdx >> 2) * 64;
    int n0 = (tileIdx & 3) * 64;
    int tx = tid & 15;             // n-group (4 cols)
    int ty = tid >> 4;             // m-group (4 rows)

    int lm  = tid >> 2;            // A load row 0..63
    int lk4 = (tid & 3) * 4;       // k offset 0,4,8,12
    int wk  = tid >> 4;            // W load k 0..15
    int wn4 = (tid & 15) * 4;      // W 4-col group

    const float* Aptr = A + (size_t)(m0 + lm)*256 + lk4;
    const float* Wptr = W + (size_t)wk*256 + n0 + wn4;

    float4 Ar = *reinterpret_cast<const float4*>(Aptr);
    float4 Wr = *reinterpret_cast<const float4*>(Wptr);

    ull aD[2][2], aA[2][2];
    aD[0][0]=0; aD[0][1]=0; aD[1][0]=0; aD[1][1]=0;
    aA[0][0]=0; aA[0][1]=0; aA[1][0]=0; aA[1][1]=0;

    #pragma unroll 1
    for (int c = 0; c < 16; c++) {
        __syncthreads();
        As[lk4+0][lm] = Ar.x; As[lk4+1][lm] = Ar.y;
        As[lk4+2][lm] = Ar.z; As[lk4+3][lm] = Ar.w;
        *reinterpret_cast<float4*>(&Ws[wk][wn4]) = Wr;
        __syncthreads();
        if (c < 15) {
            Ar = *reinterpret_cast<const float4*>(Aptr + (c+1)*16);
            Wr = *reinterpret_cast<const float4*>(Wptr + (size_t)(c+1)*16*256);
        }
        #pragma unroll
        for (int k = 0; k < 16; k++) {
            const ull* ap = reinterpret_cast<const ull*>(&As[k][ty*4]);  // 2 m-pairs
            float4 wv = *reinterpret_cast<const float4*>(&Ws[k][tx*4]);
            ull w01 = pack2(wv.x, wv.y), w23 = pack2(wv.z, wv.w);
            ull s01 = pack2(wv.y, wv.x), s23 = pack2(wv.w, wv.z);
            ull a0 = ap[0], a1 = ap[1];
            fma2(aD[0][0], a0, w01); fma2(aD[0][1], a0, w23);
            fma2(aA[0][0], a0, s01); fma2(aA[0][1], a0, s23);
            fma2(aD[1][0], a1, w01); fma2(aD[1][1], a1, w23);
            fma2(aA[1][0], a1, s01); fma2(aA[1][1], a1, s23);
        }
    }

    // Epilogue: diag/anti-diag -> rows (validated in R5/R8)
    #pragma unroll
    for (int i = 0; i < 2; i++) {
        float d0l,d0h,d1l,d1h,a0l,a0h,a1l,a1h;
        unpack2(aD[i][0], d0l, d0h); unpack2(aD[i][1], d1l, d1h);
        unpack2(aA[i][0], a0l, a0h); unpack2(aA[i][1], a1l, a1h);
        float4 r0; r0.x = d0l; r0.y = a0l; r0.z = d1l; r0.w = a1l;
        float4 r1; r1.x = a0h; r1.y = d0h; r1.z = a1h; r1.w = d1h;
        float* cp = C + (size_t)(m0 + ty*4 + 2*i)*256 + n0 + tx*4;
        *reinterpret_cast<float4*>(cp)       = r0;
        *reinterpret_cast<float4*>(cp + 256) = r1;
    }
}

// ---------------------------------------------------------------------------
// K1: uah GEMM (128 CTAs, bids 0..127 -> at most one GEMM CTA per SM)
//     + ortho (64 CTAs, bids 128..191, hides under the GEMM wave).
// ---------------------------------------------------------------------------
__global__ void __launch_bounds__(256, 2)
prep_kernel(const float* __restrict__ enc,
            const float* __restrict__ dec,
            const float* __restrict__ Ua) {
    if (blockIdx.x < 128) gemm_tile(dec, Ua, g_uah, blockIdx.x);
    else                  ortho_part(enc, blockIdx.x - 128);
}

// K2: was = ortho @ W_a (depends on ortho)
__global__ void __launch_bounds__(256, 2)
was_kernel(const float* __restrict__ Wa) {
    gemm_tile(g_ortho, Wa, g_was, blockIdx.x);
}

// ---------------------------------------------------------------------------
// K3: energy + softmax + context, per (b, 16-d tile). 128 CTAs x 256 threads.
// ---------------------------------------------------------------------------
__global__ void attn_kernel(const float* __restrict__ Va,
                            float* __restrict__ c_out,
                            float* __restrict__ e_out) {
    __shared__ float  u_sm[16][H];        // 16 KB
    __shared__ float  V_sm[H];            // 1 KB
    __shared__ float  en_sm[16][TE];      // 8 KB
    __shared__ float2 en2_sm[8][TE];      // 8 KB packed prob pairs

    int b   = blockIdx.x >> 3;
    int d0  = (blockIdx.x & 7) * 16;
    int tid = threadIdx.x;
    int warp = tid >> 5, lane = tid & 31;

    {   // u_sm: 16 rows x 256 = 1024 float4
        const float4* usrc = reinterpret_cast<const float4*>(g_uah + (size_t)(b*TD + d0)*H);
        float4* udst = reinterpret_cast<float4*>(&u_sm[0][0]);
        #pragma unroll
        for (int r = 0; r < 4; r++) udst[tid + 256*r] = usrc[tid + 256*r];
        V_sm[tid] = Va[tid];
    }
    __syncthreads();

    const float* wbase = g_was + (size_t)(b*TE)*H;

    // ---- energies: warp handles e = pass*8 + warp, 16 passes, 16 d accs ----
    float w[8];
    {
        const float* wr = wbase + warp*H;
        #pragma unroll
        for (int j = 0; j < 8; j++) w[j] = wr[lane + 32*j];
    }
    #pragma unroll 1
    for (int pass = 0; pass < 16; pass++) {
        int e = pass*8 + warp;
        float wn[8];
        if (pass < 15) {
            const float* wr = wbase + (e + 8)*H;
            #pragma unroll
            for (int j = 0; j < 8; j++) wn[j] = wr[lane + 32*j];
        }
        float a[16];
        #pragma unroll
        for (int d = 0; d < 16; d++) a[d] = 0.f;
        #pragma unroll
        for (int j = 0; j < 8; j++) {
            int hh = lane + 32*j;
            float wv = w[j];
            float v  = V_sm[hh];
            #pragma unroll
            for (int d = 0; d < 16; d++)
                a[d] += tanh_fast(wv + u_sm[d][hh]) * v;
        }
        #pragma unroll
        for (int off = 16; off; off >>= 1)
            #pragma unroll
            for (int d = 0; d < 16; d++)
                a[d] += __shfl_xor_sync(0xffffffffu, a[d], off);
        if (lane == 0) {
            #pragma unroll
            for (int d = 0; d < 16; d++) en_sm[d][e] = a[d];
        }
        #pragma unroll
        for (int j = 0; j < 8; j++) w[j] = wn[j];
    }
    __syncthreads();

    // ---- softmax over e: each warp handles rows d = warp and warp+8 ----
    #pragma unroll
    for (int dd = 0; dd < 2; dd++) {
        int d = warp + dd*8;
        float v0 = en_sm[d][lane],     v1 = en_sm[d][lane+32];
        float v2 = en_sm[d][lane+64],  v3 = en_sm[d][lane+96];
        float m = fmaxf(fmaxf(v0, v1), fmaxf(v2, v3));
        #pragma unroll
        for (int off = 16; off; off >>= 1)
            m = fmaxf(m, __shfl_xor_sync(0xffffffffu, m, off));
        v0 = __expf(v0 - m); v1 = __expf(v1 - m);
        v2 = __expf(v2 - m); v3 = __expf(v3 - m);
        float s = v0 + v1 + v2 + v3;
        #pragma unroll
        for (int off = 16; off; off >>= 1)
            s += __shfl_xor_sync(0xffffffffu, s, off);
        float inv = 1.0f / s;
        v0 *= inv; v1 *= inv; v2 *= inv; v3 *= inv;
        float* er = e_out + (size_t)(b*TD + d0 + d)*TE;
        er[lane]    = v0; er[lane+32] = v1;
        er[lane+64] = v2; er[lane+96] = v3;
        float* dst = reinterpret_cast<float*>(&en2_sm[d>>1][0]) + (d & 1);
        dst[2*lane]      = v0; dst[2*(lane+32)] = v1;
        dst[2*(lane+64)] = v2; dst[2*(lane+96)] = v3;
    }
    __syncthreads();

    // ---- context: c[d][h] = sum_e p[d][e] * ortho[b,e,h], f32x2 packed ----
    {
        int hh = tid;
        const float* orow = g_ortho + (size_t)(b*TE)*H + hh;
        ull acc[8];
        #pragma unroll
        for (int p = 0; p < 8; p++) acc[p] = 0ull;
        #pragma unroll 4
        for (int e = 0; e < TE; e++) {
            float x = orow[e*H];
            ull xx = pack2(x, x);
            #pragma unroll
            for (int p = 0; p < 8; p++)
                fma2(acc[p], xx, *reinterpret_cast<const ull*>(&en2_sm[p][e]));
        }
        float c[16];
        #pragma unroll
        for (int p = 0; p < 8; p++) unpack2(acc[p], c[2*p], c[2*p+1]);
        #pragma unroll
        for (int d = 0; d < 16; d++)
            c_out[(size_t)(b*TD + d0 + d)*H + hh] = c[d];
    }
}

// ---------------------------------------------------------------------------
extern "C" void kernel_launch(void* const* d_in, const int* in_sizes, int n_in,
                              void* d_out, int out_size) {
    const float* enc = (const float*)d_in[0];
    const float* dec = (const float*)d_in[1];
    const float* Wa  = (const float*)d_in[2];
    const float* Ua  = (const float*)d_in[3];
    const float* Va  = (const float*)d_in[4];

    float* out   = (float*)d_out;
    float* c_out = out;                    // [B, TD, H]
    float* e_out = out + (size_t)B*TD*H;   // [B, TD, TE]

    prep_kernel<<<192, 256>>>(enc, dec, Ua);   // uah gemm + ortho, overlapped
    was_kernel<<<128, 256>>>(Wa);              // was = ortho @ W_a
    attn_kernel<<<128, 256>>>(Va, c_out, e_out);
}